// round 4
// baseline (speedup 1.0000x reference)
#include <cuda_runtime.h>
#include <math.h>

// Problem constants (fixed shapes from reference)
#define BS     4
#define AN     3
#define GR     64
#define CN     13
#define FD     18
#define TN     256
#define NTAR   (BS*TN)          // 1024
#define NCAND  (7*AN*NTAR)      // 21504
#define NCELL  (BS*AN*GR*GR*GR) // 3145728

// Accumulators: 0=sum_w, 1=sum_bbox, 2=sum_cls, 3=sum_p4_set, 4=sum_softplus
__device__ double g_acc[5];
// Dedup flags for tobj cells (zero-initialized at module load; cleanup kernel
// restores zeros after each launch so graph replays are deterministic).
__device__ int g_flags[NCELL];

__constant__ float c_off[7][3] = {
    {0.f,0.f,0.f},{0.5f,0.f,0.f},{0.f,0.5f,0.f},{0.f,0.f,0.5f},
    {-0.5f,0.f,0.f},{0.f,-0.5f,0.f},{0.f,0.f,-0.5f}
};

__device__ __forceinline__ float softplusf(float x) {
    return fmaxf(x, 0.f) + log1pf(__expf(-fabsf(x)));
}
__device__ __forceinline__ float sigmoidf(float x) {
    return 1.f / (1.f + __expf(-x));
}

// Block-sum reduce; result valid on thread 0.
__device__ __forceinline__ float block_reduce(float v, float* sh) {
    __syncthreads();  // allow shared reuse across consecutive calls
    #pragma unroll
    for (int o = 16; o; o >>= 1) v += __shfl_down_sync(0xffffffffu, v, o);
    int lane = threadIdx.x & 31, w = threadIdx.x >> 5;
    if (lane == 0) sh[w] = v;
    __syncthreads();
    if (w == 0) {
        v = (lane < (int)(blockDim.x >> 5)) ? sh[lane] : 0.f;
        #pragma unroll
        for (int o = 16; o; o >>= 1) v += __shfl_down_sync(0xffffffffu, v, o);
    }
    return v;
}

// Shared candidate geometry: validity + cell index + box geometry.
__device__ __forceinline__ bool cand_geom(
    int tid, const float* __restrict__ targets, const float* __restrict__ anchor,
    int& cell, float& tbx, float& tby, float& tbz, float& rn, float& an,
    const float*& xrow)
{
    int t = tid & (NTAR - 1);
    int a = (tid >> 10) % AN;
    int o = tid / (AN * NTAR);
    const float* x = targets + t * FD;
    xrow = x;
    int b = t / TN;

    if (!(x[4] > 0.5f)) return false;                 // conf_m
    rn = x[3] * 0.25f;
    an = anchor[a] * 0.25f;
    float ratio = rn / an;
    if (!(fmaxf(ratio, 1.f / ratio) < 4.f)) return false;  // aok

    float gx = x[0] * 0.25f, gy = x[1] * 0.25f, gz = x[2] * 0.25f;

    bool fmv = true;
    if (o >= 1 && o <= 3) {
        float v = (o == 1) ? gx : (o == 2) ? gy : gz;
        fmv = ((v - floorf(v)) < 0.5f) && (v > 1.f);
    } else if (o >= 4) {
        float v0 = (o == 4) ? gx : (o == 5) ? gy : gz;
        float v = 64.f - v0;
        fmv = ((v - floorf(v)) < 0.5f) && (v > 1.f);
    }
    if (!fmv) return false;

    float fx = truncf(gx - c_off[o][0]);
    float fy = truncf(gy - c_off[o][1]);
    float fz = truncf(gz - c_off[o][2]);
    int gi = min(max(__float2int_rz(fx), 0), GR - 1);
    int gj = min(max(__float2int_rz(fy), 0), GR - 1);
    int gk = min(max(__float2int_rz(fz), 0), GR - 1);
    cell = (((b * AN + a) * GR + gk) * GR + gj) * GR + gi;
    tbx = gx - fx; tby = gy - fy; tbz = gz - fz;
    return true;
}

__global__ void init_kernel() {
    if (threadIdx.x < 5) g_acc[threadIdx.x] = 0.0;
}

__global__ void cand_kernel(const float* __restrict__ p,
                            const float* __restrict__ targets,
                            const float* __restrict__ anchor)
{
    __shared__ float sh[32];
    int tid = blockIdx.x * blockDim.x + threadIdx.x;
    float lw = 0.f, lbb = 0.f, lcls = 0.f, lp4 = 0.f;

    int cell; float tbx, tby, tbz, rn, an; const float* x;
    if (tid < NCAND && cand_geom(tid, targets, anchor, cell, tbx, tby, tbz, rn, an, x)) {
        const float* pr = p + (size_t)cell * FD;
        float pred[FD];
        #pragma unroll
        for (int i = 0; i < FD; i++) pred[i] = __ldg(pr + i);

        // pbox
        float c1x = sigmoidf(pred[0]) * 2.f - 0.5f;
        float c1y = sigmoidf(pred[1]) * 2.f - 0.5f;
        float c1z = sigmoidf(pred[2]) * 2.f - 0.5f;
        float s4  = sigmoidf(pred[3]) * 2.f;
        float r1  = s4 * s4 * an;

        // EIoU(pbox, tbox)
        const float eps = 1e-7f;
        float r2 = rn;
        float h1 = r1 * 0.5f, h2 = r2 * 0.5f;
        float lox = fmaxf(c1x - h1, tbx - h2), hix = fminf(c1x + h1, tbx + h2);
        float loy = fmaxf(c1y - h1, tby - h2), hiy = fminf(c1y + h1, tby + h2);
        float loz = fmaxf(c1z - h1, tbz - h2), hiz = fminf(c1z + h1, tbz + h2);
        float inter = fmaxf(hix - lox, 0.f) * fmaxf(hiy - loy, 0.f) * fmaxf(hiz - loz, 0.f);
        float uni = r1 * r1 * r1 + r2 * r2 * r2 - inter + eps;
        float iou = inter / uni;
        float cdx = fmaxf(c1x + h1, tbx + h2) - fminf(c1x - h1, tbx - h2);
        float cdy = fmaxf(c1y + h1, tby + h2) - fminf(c1y - h1, tby - h2);
        float cdz = fmaxf(c1z + h1, tbz + h2) - fminf(c1z - h1, tbz - h2);
        float dx = c1x - tbx, dy = c1y - tby, dz = c1z - tbz;
        float rho2 = dx * dx + dy * dy + dz * dz;
        float c2diag = cdx * cdx + cdy * cdy + cdz * cdz + eps;
        float dr = r1 - r2; float dr2 = dr * dr;
        float size_pen = dr2 / (cdx * cdx + eps) + dr2 / (cdy * cdy + eps) + dr2 / (cdz * cdz + eps);
        float ei = iou - rho2 / c2diag - size_pen;

        lw  = 1.f;
        lbb = 1.f - ei;

        // class BCE (tcls one-hot, values exactly 0/1)
        float cs = 0.f;
        #pragma unroll
        for (int c = 0; c < CN; c++) {
            float l = pred[5 + c];
            float tc = x[5 + c];
            cs += tc * softplusf(-l) + (1.f - tc) * softplusf(l);
        }
        lcls = cs;

        // tobj dedup: first valid candidate for this cell owns the -p4 correction
        if (atomicExch(&g_flags[cell], 1) == 0) lp4 = pred[4];
    }

    float v;
    v = block_reduce(lw,   sh); if (threadIdx.x == 0 && v != 0.f) atomicAdd(&g_acc[0], (double)v);
    v = block_reduce(lbb,  sh); if (threadIdx.x == 0 && v != 0.f) atomicAdd(&g_acc[1], (double)v);
    v = block_reduce(lcls, sh); if (threadIdx.x == 0 && v != 0.f) atomicAdd(&g_acc[2], (double)v);
    v = block_reduce(lp4,  sh); if (threadIdx.x == 0 && v != 0.f) atomicAdd(&g_acc[3], (double)v);
}

// Big reduction: sum softplus(p[...,4]) over all cells. 4 independent loads/thread.
__global__ void obj_kernel(const float* __restrict__ p)
{
    __shared__ float sh[32];
    int gtid = blockIdx.x * blockDim.x + threadIdx.x;
    int i0 = gtid * 4;
    float s = 0.f;
    if (i0 + 3 < NCELL) {
        float v0 = __ldg(p + i0 * FD + 4);
        float v1 = __ldg(p + (i0 + 1) * FD + 4);
        float v2 = __ldg(p + (i0 + 2) * FD + 4);
        float v3 = __ldg(p + (i0 + 3) * FD + 4);
        s = softplusf(v0) + softplusf(v1) + softplusf(v2) + softplusf(v3);
    } else {
        for (int i = i0; i < NCELL; i++) s += softplusf(__ldg(p + i * FD + 4));
    }
    float v = block_reduce(s, sh);
    if (threadIdx.x == 0) atomicAdd(&g_acc[4], (double)v);
}

__global__ void fin_kernel(float* out, int out_size)
{
    double sw   = g_acc[0];
    double sbb  = g_acc[1];
    double scls = g_acc[2];
    double sp4  = g_acc[3];
    double ssp  = g_acc[4];
    double nv = fmax(sw, 1.0);
    double lb = sbb / nv;                       // loss_bbox * 1.0
    double lc = 10.0 * scls / (nv * (double)CN);
    double lo = 20.0 * (ssp - sp4) / (double)NCELL;
    if (out_size > 0) out[0] = (float)((lb + lo + lc) * (double)BS);
    if (out_size > 1) out[1] = (float)lo;
    if (out_size > 2) out[2] = (float)lc;
}

// Restore flags to zero for every cell a valid candidate could have set.
__global__ void cleanup_kernel(const float* __restrict__ targets,
                               const float* __restrict__ anchor)
{
    int tid = blockIdx.x * blockDim.x + threadIdx.x;
    int cell; float tbx, tby, tbz, rn, an; const float* x;
    if (tid < NCAND && cand_geom(tid, targets, anchor, cell, tbx, tby, tbz, rn, an, x)) {
        g_flags[cell] = 0;
    }
}

extern "C" void kernel_launch(void* const* d_in, const int* in_sizes, int n_in,
                              void* d_out, int out_size)
{
    const float* p      = (const float*)d_in[0];
    const float* tg     = (const float*)d_in[1];
    const float* anchor = (const float*)d_in[2];
    float* out = (float*)d_out;

    init_kernel<<<1, 32>>>();
    cand_kernel<<<NCAND / 256, 256>>>(p, tg, anchor);
    obj_kernel<<<NCELL / 4 / 256, 256>>>(p);
    fin_kernel<<<1, 1>>>(out, out_size);
    cleanup_kernel<<<NCAND / 256, 256>>>(tg, anchor);
}

// round 5
// speedup vs baseline: 1.1779x; 1.1779x over previous
#include <cuda_runtime.h>
#include <math.h>

// Problem constants (fixed shapes from reference)
#define BS     4
#define AN     3
#define GR     64
#define CN     13
#define FD     18
#define TN     256
#define NTAR   (BS*TN)          // 1024
#define NCAND  (7*AN*NTAR)      // 21504
#define NCELL  (BS*AN*GR*GR*GR) // 3145728

#define CELLS_PER_THREAD 8
#define MAIN_BLOCKS (NCELL / (256 * CELLS_PER_THREAD))  // 1536
#define CAND_BLOCKS (NCAND / 256)                        // 84

// Accumulators: 0=sum_w, 1=sum_bbox, 2=sum_cls, 3=sum_p4_set, 4=sum_softplus
// Zero at module load; fin_cleanup re-zeroes after every launch (replay-safe).
__device__ double g_acc[5];
// Dedup flags for tobj cells (same invariant: zero between launches).
__device__ int g_flags[NCELL];

__constant__ float c_off[7][3] = {
    {0.f,0.f,0.f},{0.5f,0.f,0.f},{0.f,0.5f,0.f},{0.f,0.f,0.5f},
    {-0.5f,0.f,0.f},{0.f,-0.5f,0.f},{0.f,0.f,-0.5f}
};

__device__ __forceinline__ float softplusf(float x) {
    return fmaxf(x, 0.f) + log1pf(__expf(-fabsf(x)));
}
__device__ __forceinline__ float sigmoidf(float x) {
    return 1.f / (1.f + __expf(-x));
}

// Block-sum reduce; result valid on thread 0.
__device__ __forceinline__ float block_reduce(float v, float* sh) {
    __syncthreads();  // allow shared reuse across consecutive calls
    #pragma unroll
    for (int o = 16; o; o >>= 1) v += __shfl_down_sync(0xffffffffu, v, o);
    int lane = threadIdx.x & 31, w = threadIdx.x >> 5;
    if (lane == 0) sh[w] = v;
    __syncthreads();
    if (w == 0) {
        v = (lane < (int)(blockDim.x >> 5)) ? sh[lane] : 0.f;
        #pragma unroll
        for (int o = 16; o; o >>= 1) v += __shfl_down_sync(0xffffffffu, v, o);
    }
    return v;
}

// Shared candidate geometry: validity + cell index + box geometry.
__device__ __forceinline__ bool cand_geom(
    int tid, const float* __restrict__ targets, const float* __restrict__ anchor,
    int& cell, float& tbx, float& tby, float& tbz, float& rn, float& an,
    const float*& xrow)
{
    int t = tid & (NTAR - 1);
    int a = (tid >> 10) % AN;
    int o = tid / (AN * NTAR);
    const float* x = targets + t * FD;
    xrow = x;
    int b = t / TN;

    if (!(x[4] > 0.5f)) return false;                 // conf_m
    rn = x[3] * 0.25f;
    an = anchor[a] * 0.25f;
    float ratio = rn / an;
    if (!(fmaxf(ratio, 1.f / ratio) < 4.f)) return false;  // aok

    float gx = x[0] * 0.25f, gy = x[1] * 0.25f, gz = x[2] * 0.25f;

    bool fmv = true;
    if (o >= 1 && o <= 3) {
        float v = (o == 1) ? gx : (o == 2) ? gy : gz;
        fmv = ((v - floorf(v)) < 0.5f) && (v > 1.f);
    } else if (o >= 4) {
        float v0 = (o == 4) ? gx : (o == 5) ? gy : gz;
        float v = 64.f - v0;
        fmv = ((v - floorf(v)) < 0.5f) && (v > 1.f);
    }
    if (!fmv) return false;

    float fx = truncf(gx - c_off[o][0]);
    float fy = truncf(gy - c_off[o][1]);
    float fz = truncf(gz - c_off[o][2]);
    int gi = min(max(__float2int_rz(fx), 0), GR - 1);
    int gj = min(max(__float2int_rz(fy), 0), GR - 1);
    int gk = min(max(__float2int_rz(fz), 0), GR - 1);
    cell = (((b * AN + a) * GR + gk) * GR + gj) * GR + gi;
    tbx = gx - fx; tby = gy - fy; tbz = gz - fz;
    return true;
}

// Fused kernel: full-tensor softplus(p4) reduction on all blocks; candidate
// EIoU/cls/dedup work piggybacked on blocks 0..CAND_BLOCKS-1.
__global__ void __launch_bounds__(256) main_kernel(
    const float* __restrict__ p,
    const float* __restrict__ targets,
    const float* __restrict__ anchor)
{
    __shared__ float sh[32];
    int bid = blockIdx.x;

    // ---- obj part: CELLS_PER_THREAD strided channel-4 loads (exact cover) ----
    int i0 = (bid * 256 + threadIdx.x) * CELLS_PER_THREAD;
    float vobj[CELLS_PER_THREAD];
    #pragma unroll
    for (int k = 0; k < CELLS_PER_THREAD; k++)
        vobj[k] = __ldg(p + (size_t)(i0 + k) * FD + 4);
    float s = 0.f;
    #pragma unroll
    for (int k = 0; k < CELLS_PER_THREAD; k++)
        s += softplusf(vobj[k]);

    // ---- candidate part (first CAND_BLOCKS blocks only) ----
    float lw = 0.f, lbb = 0.f, lcls = 0.f, lp4 = 0.f;
    bool is_cand_block = (bid < CAND_BLOCKS);
    if (is_cand_block) {
        int tid = bid * 256 + threadIdx.x;
        int cell; float tbx, tby, tbz, rn, an; const float* x;
        if (cand_geom(tid, targets, anchor, cell, tbx, tby, tbz, rn, an, x)) {
            const float* pr = p + (size_t)cell * FD;
            float pred[FD];
            #pragma unroll
            for (int i = 0; i < FD; i++) pred[i] = __ldg(pr + i);

            // pbox
            float c1x = sigmoidf(pred[0]) * 2.f - 0.5f;
            float c1y = sigmoidf(pred[1]) * 2.f - 0.5f;
            float c1z = sigmoidf(pred[2]) * 2.f - 0.5f;
            float s4  = sigmoidf(pred[3]) * 2.f;
            float r1  = s4 * s4 * an;

            // EIoU(pbox, tbox)
            const float eps = 1e-7f;
            float r2 = rn;
            float h1 = r1 * 0.5f, h2 = r2 * 0.5f;
            float lox = fmaxf(c1x - h1, tbx - h2), hix = fminf(c1x + h1, tbx + h2);
            float loy = fmaxf(c1y - h1, tby - h2), hiy = fminf(c1y + h1, tby + h2);
            float loz = fmaxf(c1z - h1, tbz - h2), hiz = fminf(c1z + h1, tbz + h2);
            float inter = fmaxf(hix - lox, 0.f) * fmaxf(hiy - loy, 0.f) * fmaxf(hiz - loz, 0.f);
            float uni = r1 * r1 * r1 + r2 * r2 * r2 - inter + eps;
            float iou = inter / uni;
            float cdx = fmaxf(c1x + h1, tbx + h2) - fminf(c1x - h1, tbx - h2);
            float cdy = fmaxf(c1y + h1, tby + h2) - fminf(c1y - h1, tby - h2);
            float cdz = fmaxf(c1z + h1, tbz + h2) - fminf(c1z - h1, tbz - h2);
            float dx = c1x - tbx, dy = c1y - tby, dz = c1z - tbz;
            float rho2 = dx * dx + dy * dy + dz * dz;
            float c2diag = cdx * cdx + cdy * cdy + cdz * cdz + eps;
            float dr = r1 - r2; float dr2 = dr * dr;
            float size_pen = dr2 / (cdx * cdx + eps) + dr2 / (cdy * cdy + eps) + dr2 / (cdz * cdz + eps);
            float ei = iou - rho2 / c2diag - size_pen;

            lw  = 1.f;
            lbb = 1.f - ei;

            // class BCE (tcls one-hot 0/1)
            float cs = 0.f;
            #pragma unroll
            for (int c = 0; c < CN; c++) {
                float l = pred[5 + c];
                float tc = x[5 + c];
                cs += tc * softplusf(-l) + (1.f - tc) * softplusf(l);
            }
            lcls = cs;

            // tobj dedup: winner value depends only on the cell -> deterministic
            if (atomicExch(&g_flags[cell], 1) == 0) lp4 = pred[4];
        }
    }

    // ---- reductions ----
    float v;
    v = block_reduce(s, sh);
    if (threadIdx.x == 0) atomicAdd(&g_acc[4], (double)v);
    if (is_cand_block) {
        v = block_reduce(lw,   sh); if (threadIdx.x == 0 && v != 0.f) atomicAdd(&g_acc[0], (double)v);
        v = block_reduce(lbb,  sh); if (threadIdx.x == 0 && v != 0.f) atomicAdd(&g_acc[1], (double)v);
        v = block_reduce(lcls, sh); if (threadIdx.x == 0 && v != 0.f) atomicAdd(&g_acc[2], (double)v);
        v = block_reduce(lp4,  sh); if (threadIdx.x == 0 && v != 0.f) atomicAdd(&g_acc[3], (double)v);
    }
}

// Finalize outputs + restore all device state to zero for the next replay.
// Blocks 0..CAND_BLOCKS-1: clear dedup flags. Block CAND_BLOCKS: write
// outputs then reset accumulators.
__global__ void fin_cleanup_kernel(float* out, int out_size,
                                   const float* __restrict__ targets,
                                   const float* __restrict__ anchor)
{
    int bid = blockIdx.x;
    if (bid < CAND_BLOCKS) {
        int tid = bid * 256 + threadIdx.x;
        int cell; float tbx, tby, tbz, rn, an; const float* x;
        if (cand_geom(tid, targets, anchor, cell, tbx, tby, tbz, rn, an, x))
            g_flags[cell] = 0;
    } else if (threadIdx.x == 0) {
        double sw   = g_acc[0];
        double sbb  = g_acc[1];
        double scls = g_acc[2];
        double sp4  = g_acc[3];
        double ssp  = g_acc[4];
        double nv = fmax(sw, 1.0);
        double lb = sbb / nv;                       // loss_bbox * 1.0
        double lc = 10.0 * scls / (nv * (double)CN);
        double lo = 20.0 * (ssp - sp4) / (double)NCELL;
        if (out_size > 0) out[0] = (float)((lb + lo + lc) * (double)BS);
        if (out_size > 1) out[1] = (float)lo;
        if (out_size > 2) out[2] = (float)lc;
        #pragma unroll
        for (int i = 0; i < 5; i++) g_acc[i] = 0.0;
    }
}

extern "C" void kernel_launch(void* const* d_in, const int* in_sizes, int n_in,
                              void* d_out, int out_size)
{
    const float* p      = (const float*)d_in[0];
    const float* tg     = (const float*)d_in[1];
    const float* anchor = (const float*)d_in[2];
    float* out = (float*)d_out;

    main_kernel<<<MAIN_BLOCKS, 256>>>(p, tg, anchor);
    fin_cleanup_kernel<<<CAND_BLOCKS + 1, 256>>>(out, out_size, tg, anchor);
}